// round 15
// baseline (speedup 1.0000x reference)
#include <cuda_runtime.h>
#include <cstdint>

// PolyLoss single-launch, range-reduced raster + 2-LEVEL completion tree.
// Coords ∈ [32,96): rows 32..95 only; row mask = ONE 64-bit word (px 32..95).
// One block (128 thr = 4 warps) per (b,k): tid -> (pg = tid&1, row = 32+(tid>>1)).
// Completion: 512 same-address counter arrivals serialize in the LTS atomic
// ALU (~7 cyc/op measured R13) => ~2us drain on the critical path. Tree:
// 32 padded sub-counters (16 arrivals each, parallel LTS slices) -> 1 master
// (32 arrivals). Last block folds 512 g_part partials and resets state.

#define NB 4
#define NK 128
#define NC 32
#define NH 128
#define NW 128
#define NBLK (NB * NK)   // 512
#define NT 128
#define NSUB 32
#define GROUP (NBLK / NSUB)   // 16

typedef unsigned long long ull;

struct PaddedCnt { unsigned int c; unsigned int pad[31]; };  // one 128B line each

__device__ float4 g_part[NBLK];          // x=iou*m, y=reg, z=maskf
__device__ PaddedCnt g_sub[NSUB];        // level-1 counters (zero-init)
__device__ unsigned int g_master;        // level-2 counter (zero-init)

__device__ __forceinline__ ull shr64_clamp(unsigned int amt) {
    // ~0ull >> amt with PTX clamp semantics (amt >= 64 -> 0)
    ull r;
    asm("shr.u64 %0, %1, %2;" : "=l"(r) : "l"(~0ull), "r"(amt));
    return r;
}

__global__ void __launch_bounds__(NT) poly_loss_kernel(
    const float* __restrict__ output,   // (B,C,H,W)
    const int*   __restrict__ mask,     // (B,K)
    const int*   __restrict__ ind,      // (B,K)
    const float* __restrict__ target,   // (B,K,C)
    float*       __restrict__ out)
{
    const int poly = blockIdx.x;            // 0..511
    const int b = poly >> 7, k = poly & 127;
    const int tid = threadIdx.x;
    const int lane = tid & 31, wid = tid >> 5;

    __shared__ float  s_xy[64];             // [0..31]=pred, [32..63]=gt coords
    __shared__ float4 e_pk[32];             // edge: x=x0, y=ymin, z=ymax, w=slope
    __shared__ int    s_red[4];
    __shared__ float  s_reg;
    __shared__ bool   s_last;

    if (tid < NC) {
        int idx = __ldg(&ind[b * NK + k]);
        s_xy[tid]      = __ldg(&output[((b * NC + tid) * (NH * NW)) + idx]);
        s_xy[32 + tid] = __ldg(&target[(b * NK + k) * NC + tid]);
    }
    __syncthreads();

    const float maskf = (float)__ldg(&mask[b * NK + k]);

    // ---- edge precompute + reg-loss partial (threads 0..31) ----
    if (tid < 32) {
        const int base = (tid >> 4) << 5;   // 0 = pred, 32 = gt
        const int v  = tid & 15;
        const int v2 = (v + 1) & 15;
        float x1 = s_xy[base + 2 * v]      + 32.f;
        float y1 = s_xy[base + 2 * v + 1]  + 32.f;
        float x2 = s_xy[base + 2 * v2]     + 32.f;
        float y2 = s_xy[base + 2 * v2 + 1] + 32.f;
        float dy = y2 - y1;
        float denom = (dy == 0.f) ? 1.f : dy;
        float slope = (x2 - x1) / denom;
        float x0 = fmaf(-y1, slope, x1);
        // crossing == (ymin <= py) && (py < ymax)
        e_pk[tid] = make_float4(x0, fminf(y1, y2), fmaxf(y1, y2), slope);

        float d = fabsf(s_xy[tid] * maskf - s_xy[32 + tid] * maskf);
        #pragma unroll
        for (int o = 16; o; o >>= 1) d += __shfl_down_sync(0xffffffffu, d, o);
        if (tid == 0) s_reg = d;
    }
    __syncthreads();

    const int   pg    = tid & 1;                  // 0 = pred, 1 = gt
    const float py    = (float)(32 + (tid >> 1)); // raster row in [32,96)
    const int   ebase = pg << 4;

    ull word = 0;
    #pragma unroll
    for (int e = 0; e < 16; e++) {
        float4 E = e_pk[ebase + e];
        bool crossing = (E.y <= py) & (py < E.z);
        float xint = fmaf(py, E.w, E.x);
        // shift amount = 96 - ceil(clamp(xint,32,96)); non-crossing -> 64 (mask 0)
        unsigned int amt = (unsigned)(96 - __float2int_ru(fminf(fmaxf(xint, 32.f), 96.f)));
        amt = crossing ? amt : 64u;
        word ^= shr64_clamp(amt);
    }

    // partner (other polygon, same row) word
    ull other = __shfl_xor_sync(0xffffffffu, word, 1);
    int icnt = __popcll(word & other);      // counted by both partners -> /2 later
    int cnt  = __popcll(word);
    int packed = icnt | (cnt << 16);

    #pragma unroll
    for (int o = 16; o; o >>= 1)
        packed += __shfl_down_sync(0xffffffffu, packed, o);
    if (lane == 0) s_red[wid] = packed;
    __syncthreads();

    if (tid == 0) {
        int tot = s_red[0] + s_red[1] + s_red[2] + s_red[3];
        float inter = (float)((tot & 0xFFFF) >> 1);
        float cnts  = (float)((unsigned)tot >> 16);     // cp + cg
        float un    = cnts - inter;
        float iou   = inter / (un + 1e-6f);
        g_part[poly] = make_float4(iou * maskf, s_reg, maskf, 0.f);
        __threadfence();                     // release g_part before arrival
        bool last = false;
        unsigned int olds = atomicAdd(&g_sub[poly & (NSUB - 1)].c, 1u);
        if (olds == GROUP - 1) {             // promoter: this sub-group done
            __threadfence();
            unsigned int oldm = atomicAdd(&g_master, 1u);
            last = (oldm == NSUB - 1);
            if (last) __threadfence();       // acquire before reading g_part
        }
        s_last = last;
    }
    __syncthreads();

    if (s_last) {
        // final reduction over 512 partials: four per thread
        float a0 = 0.f, a1 = 0.f, a2 = 0.f;
        #pragma unroll
        for (int i = 0; i < NBLK / NT; i++) {
            float4 p = g_part[tid + i * NT];
            a0 += p.x; a1 += p.y; a2 += p.z;
        }
        #pragma unroll
        for (int o = 16; o; o >>= 1) {
            a0 += __shfl_down_sync(0xffffffffu, a0, o);
            a1 += __shfl_down_sync(0xffffffffu, a1, o);
            a2 += __shfl_down_sync(0xffffffffu, a2, o);
        }
        __shared__ float s_f[3][4];
        if (lane == 0) { s_f[0][wid] = a0; s_f[1][wid] = a1; s_f[2][wid] = a2; }
        __syncthreads();
        if (tid == 0) {
            float t0 = 0.f, t1 = 0.f, t2 = 0.f;
            #pragma unroll
            for (int w = 0; w < 4; w++) { t0 += s_f[0][w]; t1 += s_f[1][w]; t2 += s_f[2][w]; }
            float inv = 1.f / (t2 + 1e-6f);
            out[0] = (1.f - t0 * inv) + t1 * inv;
        }
        // reset counters for next graph replay (one thread per counter)
        if (tid < NSUB) g_sub[tid].c = 0;
        if (tid == NSUB) g_master = 0;
    }
}

extern "C" void kernel_launch(void* const* d_in, const int* in_sizes, int n_in,
                              void* d_out, int out_size) {
    const float* output = (const float*)d_in[0];
    const int*   mask   = (const int*)d_in[1];
    const int*   ind    = (const int*)d_in[2];
    const float* target = (const float*)d_in[3];
    float* out = (float*)d_out;

    poly_loss_kernel<<<NBLK, NT>>>(output, mask, ind, target, out);
}

// round 16
// speedup vs baseline: 1.0403x; 1.0403x over previous
#include <cuda_runtime.h>
#include <cstdint>

// PolyLoss single-launch, range-reduced raster (champion R8/R14 structure).
// Coords ∈ [32,96): rows 32..95 only; row mask = ONE 64-bit word (px 32..95).
// One block (128 thr = 4 warps) per (b,k): tid -> (pg = tid&1, row = 32+(tid>>1)).
// Per-block partials to g_part[poly] (distinct addresses); plain single
// counter + last-block fold (2-level tree and shared-address atomics both
// measured SLOWER, R13/R15). Graph-replayable: last block resets the counter.

#define NB 4
#define NK 128
#define NC 32
#define NH 128
#define NW 128
#define NBLK (NB * NK)   // 512
#define NT 128

typedef unsigned long long ull;

__device__ float4 g_part[NBLK];          // x=iou*m, y=reg, z=maskf
__device__ unsigned int g_count;         // reset by last block each launch

__device__ __forceinline__ ull shr64_clamp(unsigned int amt) {
    // ~0ull >> amt with PTX clamp semantics (amt >= 64 -> 0)
    ull r;
    asm("shr.u64 %0, %1, %2;" : "=l"(r) : "l"(~0ull), "r"(amt));
    return r;
}

__global__ void __launch_bounds__(NT) poly_loss_kernel(
    const float* __restrict__ output,   // (B,C,H,W)
    const int*   __restrict__ mask,     // (B,K)
    const int*   __restrict__ ind,      // (B,K)
    const float* __restrict__ target,   // (B,K,C)
    float*       __restrict__ out)
{
    const int poly = blockIdx.x;            // 0..511
    const int b = poly >> 7, k = poly & 127;
    const int tid = threadIdx.x;
    const int lane = tid & 31, wid = tid >> 5;

    __shared__ float  s_xy[64];             // [0..31]=pred, [32..63]=gt coords
    __shared__ float4 e_pk[32];             // edge: x=x0, y=ymin, z=ymax, w=slope
    __shared__ int    s_red[4];
    __shared__ float  s_reg;
    __shared__ bool   s_last;

    // mask load hoisted: overlaps the gather chain below
    const float maskf = (float)__ldg(&mask[b * NK + k]);

    // prologue loads spread over 64 threads (one each)
    if (tid < 64) {
        if (tid < NC) {
            int idx = __ldg(&ind[b * NK + k]);
            s_xy[tid] = __ldg(&output[((b * NC + tid) * (NH * NW)) + idx]);
        } else {
            s_xy[tid] = __ldg(&target[(b * NK + k) * NC + (tid - 32)]);
        }
    }
    __syncthreads();

    // ---- edge precompute + reg-loss partial (threads 0..31) ----
    if (tid < 32) {
        const int base = (tid >> 4) << 5;   // 0 = pred, 32 = gt
        const int v  = tid & 15;
        const int v2 = (v + 1) & 15;
        float x1 = s_xy[base + 2 * v]      + 32.f;
        float y1 = s_xy[base + 2 * v + 1]  + 32.f;
        float x2 = s_xy[base + 2 * v2]     + 32.f;
        float y2 = s_xy[base + 2 * v2 + 1] + 32.f;
        float dy = y2 - y1;
        float denom = (dy == 0.f) ? 1.f : dy;
        float slope = (x2 - x1) / denom;
        float x0 = fmaf(-y1, slope, x1);
        // crossing == (ymin <= py) && (py < ymax)
        e_pk[tid] = make_float4(x0, fminf(y1, y2), fmaxf(y1, y2), slope);

        float d = fabsf(s_xy[tid] * maskf - s_xy[32 + tid] * maskf);
        #pragma unroll
        for (int o = 16; o; o >>= 1) d += __shfl_down_sync(0xffffffffu, d, o);
        if (tid == 0) s_reg = d;
    }
    __syncthreads();

    const int   pg    = tid & 1;                  // 0 = pred, 1 = gt
    const float py    = (float)(32 + (tid >> 1)); // raster row in [32,96)
    const int   ebase = pg << 4;

    ull word = 0;
    #pragma unroll
    for (int e = 0; e < 16; e++) {
        float4 E = e_pk[ebase + e];
        bool crossing = (E.y <= py) & (py < E.z);
        float xint = fmaf(py, E.w, E.x);
        // shift amount = 96 - ceil(clamp(xint,32,96)); non-crossing -> 64 (mask 0)
        unsigned int amt = (unsigned)(96 - __float2int_ru(fminf(fmaxf(xint, 32.f), 96.f)));
        amt = crossing ? amt : 64u;
        word ^= shr64_clamp(amt);
    }

    // partner (other polygon, same row) word
    ull other = __shfl_xor_sync(0xffffffffu, word, 1);
    int icnt = __popcll(word & other);      // counted by both partners -> /2 later
    int cnt  = __popcll(word);
    int packed = icnt | (cnt << 16);

    #pragma unroll
    for (int o = 16; o; o >>= 1)
        packed += __shfl_down_sync(0xffffffffu, packed, o);
    if (lane == 0) s_red[wid] = packed;
    __syncthreads();

    if (tid == 0) {
        int tot = s_red[0] + s_red[1] + s_red[2] + s_red[3];
        float inter = (float)((tot & 0xFFFF) >> 1);
        float cnts  = (float)((unsigned)tot >> 16);     // cp + cg
        float un    = cnts - inter;
        float iou   = inter / (un + 1e-6f);
        g_part[poly] = make_float4(iou * maskf, s_reg, maskf, 0.f);
        __threadfence();
        unsigned int old = atomicAdd(&g_count, 1u);
        s_last = (old == NBLK - 1);
    }
    __syncthreads();

    if (s_last) {
        // final reduction over 512 partials: four per thread
        float a0 = 0.f, a1 = 0.f, a2 = 0.f;
        #pragma unroll
        for (int i = 0; i < NBLK / NT; i++) {
            float4 p = g_part[tid + i * NT];
            a0 += p.x; a1 += p.y; a2 += p.z;
        }
        #pragma unroll
        for (int o = 16; o; o >>= 1) {
            a0 += __shfl_down_sync(0xffffffffu, a0, o);
            a1 += __shfl_down_sync(0xffffffffu, a1, o);
            a2 += __shfl_down_sync(0xffffffffu, a2, o);
        }
        __shared__ float s_f[3][4];
        if (lane == 0) { s_f[0][wid] = a0; s_f[1][wid] = a1; s_f[2][wid] = a2; }
        __syncthreads();
        if (tid == 0) {
            float t0 = 0.f, t1 = 0.f, t2 = 0.f;
            #pragma unroll
            for (int w = 0; w < 4; w++) { t0 += s_f[0][w]; t1 += s_f[1][w]; t2 += s_f[2][w]; }
            float inv = 1.f / (t2 + 1e-6f);
            out[0] = (1.f - t0 * inv) + t1 * inv;
            g_count = 0;   // reset for next graph replay
        }
    }
}

extern "C" void kernel_launch(void* const* d_in, const int* in_sizes, int n_in,
                              void* d_out, int out_size) {
    const float* output = (const float*)d_in[0];
    const int*   mask   = (const int*)d_in[1];
    const int*   ind    = (const int*)d_in[2];
    const float* target = (const float*)d_in[3];
    float* out = (float*)d_out;

    poly_loss_kernel<<<NBLK, NT>>>(output, mask, ind, target, out);
}

// round 17
// speedup vs baseline: 1.1051x; 1.0623x over previous
#include <cuda_runtime.h>
#include <cstdint>

// PolyLoss single-launch, range-reduced raster (champion R8/R14 structure)
// + acq_rel counter atomic replacing __threadfence (MEMBAR removed from tail).
// Coords ∈ [32,96): rows 32..95 only; row mask = ONE 64-bit word (px 32..95).
// One block (128 thr = 4 warps) per (b,k): tid -> (pg = tid&1, row = 32+(tid>>1)).
// Per-block partials to g_part[poly] (distinct addresses); plain single
// counter + last-block fold (tree/shared-address atomics measured slower).
// Graph-replayable: last block resets the counter.

#define NB 4
#define NK 128
#define NC 32
#define NH 128
#define NW 128
#define NBLK (NB * NK)   // 512
#define NT 128

typedef unsigned long long ull;

__device__ float4 g_part[NBLK];          // x=iou*m, y=reg, z=maskf
__device__ unsigned int g_count;         // reset by last block each launch

__device__ __forceinline__ ull shr64_clamp(unsigned int amt) {
    // ~0ull >> amt with PTX clamp semantics (amt >= 64 -> 0)
    ull r;
    asm("shr.u64 %0, %1, %2;" : "=l"(r) : "l"(~0ull), "r"(amt));
    return r;
}

__device__ __forceinline__ unsigned int atom_add_acq_rel(unsigned int* p, unsigned int v) {
    unsigned int old;
    asm volatile("atom.acq_rel.gpu.global.add.u32 %0, [%1], %2;"
                 : "=r"(old) : "l"(p), "r"(v) : "memory");
    return old;
}

__global__ void __launch_bounds__(NT) poly_loss_kernel(
    const float* __restrict__ output,   // (B,C,H,W)
    const int*   __restrict__ mask,     // (B,K)
    const int*   __restrict__ ind,      // (B,K)
    const float* __restrict__ target,   // (B,K,C)
    float*       __restrict__ out)
{
    const int poly = blockIdx.x;            // 0..511
    const int b = poly >> 7, k = poly & 127;
    const int tid = threadIdx.x;
    const int lane = tid & 31, wid = tid >> 5;

    __shared__ float  s_xy[64];             // [0..31]=pred, [32..63]=gt coords
    __shared__ float4 e_pk[32];             // edge: x=x0, y=ymin, z=ymax, w=slope
    __shared__ int    s_red[4];
    __shared__ float  s_reg;
    __shared__ bool   s_last;

    if (tid < NC) {
        int idx = __ldg(&ind[b * NK + k]);
        s_xy[tid]      = __ldg(&output[((b * NC + tid) * (NH * NW)) + idx]);
        s_xy[32 + tid] = __ldg(&target[(b * NK + k) * NC + tid]);
    }
    __syncthreads();

    const float maskf = (float)__ldg(&mask[b * NK + k]);

    // ---- edge precompute + reg-loss partial (threads 0..31) ----
    if (tid < 32) {
        const int base = (tid >> 4) << 5;   // 0 = pred, 32 = gt
        const int v  = tid & 15;
        const int v2 = (v + 1) & 15;
        float x1 = s_xy[base + 2 * v]      + 32.f;
        float y1 = s_xy[base + 2 * v + 1]  + 32.f;
        float x2 = s_xy[base + 2 * v2]     + 32.f;
        float y2 = s_xy[base + 2 * v2 + 1] + 32.f;
        float dy = y2 - y1;
        float denom = (dy == 0.f) ? 1.f : dy;
        float slope = (x2 - x1) / denom;
        float x0 = fmaf(-y1, slope, x1);
        // crossing == (ymin <= py) && (py < ymax)
        e_pk[tid] = make_float4(x0, fminf(y1, y2), fmaxf(y1, y2), slope);

        float d = fabsf(s_xy[tid] * maskf - s_xy[32 + tid] * maskf);
        #pragma unroll
        for (int o = 16; o; o >>= 1) d += __shfl_down_sync(0xffffffffu, d, o);
        if (tid == 0) s_reg = d;
    }
    __syncthreads();

    const int   pg    = tid & 1;                  // 0 = pred, 1 = gt
    const float py    = (float)(32 + (tid >> 1)); // raster row in [32,96)
    const int   ebase = pg << 4;

    ull word = 0;
    #pragma unroll
    for (int e = 0; e < 16; e++) {
        float4 E = e_pk[ebase + e];
        bool crossing = (E.y <= py) & (py < E.z);
        float xint = fmaf(py, E.w, E.x);
        // shift amount = 96 - ceil(clamp(xint,32,96)); non-crossing -> 64 (mask 0)
        unsigned int amt = (unsigned)(96 - __float2int_ru(fminf(fmaxf(xint, 32.f), 96.f)));
        amt = crossing ? amt : 64u;
        word ^= shr64_clamp(amt);
    }

    // partner (other polygon, same row) word
    ull other = __shfl_xor_sync(0xffffffffu, word, 1);
    int icnt = __popcll(word & other);      // counted by both partners -> /2 later
    int cnt  = __popcll(word);
    int packed = icnt | (cnt << 16);

    #pragma unroll
    for (int o = 16; o; o >>= 1)
        packed += __shfl_down_sync(0xffffffffu, packed, o);
    if (lane == 0) s_red[wid] = packed;
    __syncthreads();

    if (tid == 0) {
        int tot = s_red[0] + s_red[1] + s_red[2] + s_red[3];
        float inter = (float)((tot & 0xFFFF) >> 1);
        float cnts  = (float)((unsigned)tot >> 16);     // cp + cg
        float un    = cnts - inter;
        float iou   = inter / (un + 1e-6f);
        g_part[poly] = make_float4(iou * maskf, s_reg, maskf, 0.f);
        // acq_rel atomic: releases the g_part store, acquires for the winner's
        // subsequent g_part reads — no standalone __threadfence needed.
        unsigned int old = atom_add_acq_rel(&g_count, 1u);
        s_last = (old == NBLK - 1);
    }
    __syncthreads();

    if (s_last) {
        // final reduction over 512 partials: four per thread
        float a0 = 0.f, a1 = 0.f, a2 = 0.f;
        #pragma unroll
        for (int i = 0; i < NBLK / NT; i++) {
            float4 p = g_part[tid + i * NT];
            a0 += p.x; a1 += p.y; a2 += p.z;
        }
        #pragma unroll
        for (int o = 16; o; o >>= 1) {
            a0 += __shfl_down_sync(0xffffffffu, a0, o);
            a1 += __shfl_down_sync(0xffffffffu, a1, o);
            a2 += __shfl_down_sync(0xffffffffu, a2, o);
        }
        __shared__ float s_f[3][4];
        if (lane == 0) { s_f[0][wid] = a0; s_f[1][wid] = a1; s_f[2][wid] = a2; }
        __syncthreads();
        if (tid == 0) {
            float t0 = 0.f, t1 = 0.f, t2 = 0.f;
            #pragma unroll
            for (int w = 0; w < 4; w++) { t0 += s_f[0][w]; t1 += s_f[1][w]; t2 += s_f[2][w]; }
            float inv = 1.f / (t2 + 1e-6f);
            out[0] = (1.f - t0 * inv) + t1 * inv;
            g_count = 0;   // reset for next graph replay
        }
    }
}

extern "C" void kernel_launch(void* const* d_in, const int* in_sizes, int n_in,
                              void* d_out, int out_size) {
    const float* output = (const float*)d_in[0];
    const int*   mask   = (const int*)d_in[1];
    const int*   ind    = (const int*)d_in[2];
    const float* target = (const float*)d_in[3];
    float* out = (float*)d_out;

    poly_loss_kernel<<<NBLK, NT>>>(output, mask, ind, target, out);
}